// round 2
// baseline (speedup 1.0000x reference)
#include <cuda_runtime.h>
#include <math.h>

// Problem constants
#define BTOT 32768      // BS*T = 128*256
#define SD   512        // STATE_DIM
#define NAG  8
#define FEAT 64
#define MEMB 32         // MIX_EMB
#define EMB  32
#define HYP  256

// ---------------- global scratch (no allocations allowed) ----------------
__device__ float g_Y [BTOT * SD];    // 64 MB  : per-row embedded state y (B,512)
__device__ float g_H1[BTOT * HYP];   // 32 MB  : relu(y@W1a+b1a)
__device__ float g_HF[BTOT * HYP];   // 32 MB  : relu(y@Wfa+bfa)
__device__ float g_W1[BTOT * 256];   // 32 MB  : abs(H1@W1b+b1b)  (B, 8*32)
__device__ float g_B1[BTOT * EMB];   // 4 MB   : y@Wb1+bb1
__device__ float g_Hv[BTOT * EMB];   // 4 MB   : relu(y@Wv1+bv1)

// =========================================================================
// K1: per-row token embed:  s(B,8,64) -> e=relu(s@W_tok+b) -> y=relu(e@W_yfc+b)
// one thread per (row, agent); 64 threads = 8 rows per block
// =========================================================================
__global__ __launch_bounds__(64) void k1_embed(
    const float* __restrict__ states,
    const float* __restrict__ Wt, const float* __restrict__ bt,
    const float* __restrict__ Wy, const float* __restrict__ by)
{
    __shared__ float s_sm[8 * 520];       // 8 rows, per-agent stride 65 (bank-conflict-free)
    __shared__ float wt_sm[64 * 32];
    __shared__ float wy_sm[32 * 64];
    __shared__ float bt_sm[32];
    __shared__ float by_sm[64];

    const int tid = threadIdx.x;

    {   // stage weights
        const float4* Wt4 = (const float4*)Wt;
        float4* d = (float4*)wt_sm;
        for (int i = tid; i < 512; i += 64) d[i] = Wt4[i];
        const float4* Wy4 = (const float4*)Wy;
        float4* d2 = (float4*)wy_sm;
        for (int i = tid; i < 512; i += 64) d2[i] = Wy4[i];
        if (tid < 32) bt_sm[tid] = bt[tid];
        by_sm[tid] = by[tid];
    }
    {   // stage 8 rows of states, padded layout: [row*520 + agent*65 + k]
        const float4* S4 = (const float4*)(states + (size_t)blockIdx.x * 8 * SD);
        #pragma unroll
        for (int i = 0; i < 16; i++) {
            int f4 = tid + i * 64;            // 0..1023
            float4 v = S4[f4];
            int row = f4 >> 7;                // /128 float4 per row
            int e0  = (f4 & 127) * 4;         // element within row
            int a   = e0 >> 6;
            int k   = e0 & 63;
            float* dp = &s_sm[row * 520 + a * 65 + k];
            dp[0] = v.x; dp[1] = v.y; dp[2] = v.z; dp[3] = v.w;
        }
    }
    __syncthreads();

    const int r = tid >> 3, a = tid & 7;
    const float* srow = &s_sm[r * 520 + a * 65];

    float e[32];
    #pragma unroll
    for (int j = 0; j < 32; j++) e[j] = bt_sm[j];
    #pragma unroll 8
    for (int k = 0; k < 64; k++) {
        float sv = srow[k];
        const float4* wrow = (const float4*)&wt_sm[k * 32];
        #pragma unroll
        for (int j4 = 0; j4 < 8; j4++) {
            float4 w = wrow[j4];
            e[j4*4+0] += sv * w.x; e[j4*4+1] += sv * w.y;
            e[j4*4+2] += sv * w.z; e[j4*4+3] += sv * w.w;
        }
    }
    #pragma unroll
    for (int j = 0; j < 32; j++) e[j] = fmaxf(e[j], 0.f);

    float y[64];
    #pragma unroll
    for (int c = 0; c < 64; c++) y[c] = by_sm[c];
    #pragma unroll 4
    for (int j = 0; j < 32; j++) {
        float ev = e[j];
        const float4* wrow = (const float4*)&wy_sm[j * 64];
        #pragma unroll
        for (int c4 = 0; c4 < 16; c4++) {
            float4 w = wrow[c4];
            y[c4*4+0] += ev * w.x; y[c4*4+1] += ev * w.y;
            y[c4*4+2] += ev * w.z; y[c4*4+3] += ev * w.w;
        }
    }
    size_t row_g = (size_t)blockIdx.x * 8 + r;
    float4* out = (float4*)(g_Y + row_g * SD + a * 64);
    #pragma unroll
    for (int c4 = 0; c4 < 16; c4++) {
        float4 o;
        o.x = fmaxf(y[c4*4+0], 0.f); o.y = fmaxf(y[c4*4+1], 0.f);
        o.z = fmaxf(y[c4*4+2], 0.f); o.w = fmaxf(y[c4*4+3], 0.f);
        out[c4] = o;
    }
}

// =========================================================================
// K2: fused hypernet GEMM.  C(B,576) = Y(B,512) @ [W1a | Wfa | Wb1 | Wv1]
//   cols   0..255 -> g_H1 = relu(.+b1a)
//   cols 256..511 -> g_HF = relu(.+bfa)
//   cols 512..543 -> g_B1 =      .+bb1
//   cols 544..575 -> g_Hv = relu(.+bv1)
// BM=128, BN=64, BK=16, 256 threads, 8x4 per thread
// =========================================================================
__global__ __launch_bounds__(256) void k2_gemm(
    const float* __restrict__ W1a, const float* __restrict__ b1a,
    const float* __restrict__ Wfa, const float* __restrict__ bfa,
    const float* __restrict__ Wb1, const float* __restrict__ bb1,
    const float* __restrict__ Wv1, const float* __restrict__ bv1)
{
    __shared__ float As[16 * 128];
    __shared__ float Bs[16 * 64];

    const int tid  = threadIdx.x;
    const int txn  = tid & 15;          // n-group (4 cols)
    const int tym  = tid >> 4;          // m-group (8 rows)
    const int mbase = blockIdx.y * 128;
    const int nbase = blockIdx.x * 64;

    // B-tile load coords (fixed region per thread: column never changes)
    const int brow = tid >> 4;          // k-row within tile
    const int bc4  = tid & 15;
    const int nb   = nbase + bc4 * 4;
    const float* Wp; int ld, nl;
    if (nb < 256)      { Wp = W1a; ld = 256; nl = nb;       }
    else if (nb < 512) { Wp = Wfa; ld = 256; nl = nb - 256; }
    else if (nb < 544) { Wp = Wb1; ld = 32;  nl = nb - 512; }
    else               { Wp = Wv1; ld = 32;  nl = nb - 544; }
    const float* bsrc = Wp + (size_t)brow * ld + nl;

    float acc[8][4];
    #pragma unroll
    for (int i = 0; i < 8; i++)
        #pragma unroll
        for (int j = 0; j < 4; j++) acc[i][j] = 0.f;

    for (int kt = 0; kt < SD / 16; kt++) {
        #pragma unroll
        for (int i = 0; i < 2; i++) {          // A tile: 512 float4
            int f4  = tid + i * 256;
            int row = f4 >> 2;
            int kk  = (f4 & 3) * 4;
            float4 v = *(const float4*)(g_Y + (size_t)(mbase + row) * SD + kt * 16 + kk);
            As[(kk+0)*128 + row] = v.x;
            As[(kk+1)*128 + row] = v.y;
            As[(kk+2)*128 + row] = v.z;
            As[(kk+3)*128 + row] = v.w;
        }
        {
            float4 v = *(const float4*)(bsrc + (size_t)kt * 16 * ld);
            *(float4*)&Bs[brow * 64 + bc4 * 4] = v;
        }
        __syncthreads();
        #pragma unroll
        for (int k = 0; k < 16; k++) {
            float4 a0 = *(const float4*)&As[k * 128 + tym * 8];
            float4 a1 = *(const float4*)&As[k * 128 + tym * 8 + 4];
            float4 b  = *(const float4*)&Bs[k * 64 + txn * 4];
            float am[8] = {a0.x, a0.y, a0.z, a0.w, a1.x, a1.y, a1.z, a1.w};
            float bn[4] = {b.x, b.y, b.z, b.w};
            #pragma unroll
            for (int i = 0; i < 8; i++)
                #pragma unroll
                for (int j = 0; j < 4; j++) acc[i][j] += am[i] * bn[j];
        }
        __syncthreads();
    }

    #pragma unroll
    for (int j = 0; j < 4; j++) {
        const int n = nbase + txn * 4 + j;
        const float* bias; float* dst; int dld, nl2; bool dorelu = true;
        if (n < 256)      { bias = b1a; dst = g_H1; dld = 256; nl2 = n;       }
        else if (n < 512) { bias = bfa; dst = g_HF; dld = 256; nl2 = n - 256; }
        else if (n < 544) { bias = bb1; dst = g_B1; dld = 32;  nl2 = n - 512; dorelu = false; }
        else              { bias = bv1; dst = g_Hv; dld = 32;  nl2 = n - 544; }
        const float bv = bias[nl2];
        #pragma unroll
        for (int i = 0; i < 8; i++) {
            int m = mbase + tym * 8 + i;
            float v = acc[i][j] + bv;
            if (dorelu) v = fmaxf(v, 0.f);
            dst[(size_t)m * dld + nl2] = v;
        }
    }
}

// =========================================================================
// K3: g_W1(B,256) = abs( g_H1(B,256) @ W1b(256,256) + b1b )
// same tiling as K2
// =========================================================================
__global__ __launch_bounds__(256) void k3_gemm(
    const float* __restrict__ W1b, const float* __restrict__ b1b)
{
    __shared__ float As[16 * 128];
    __shared__ float Bs[16 * 64];

    const int tid  = threadIdx.x;
    const int txn  = tid & 15;
    const int tym  = tid >> 4;
    const int mbase = blockIdx.y * 128;
    const int nbase = blockIdx.x * 64;
    const int brow = tid >> 4;
    const int bc4  = tid & 15;
    const float* bsrc = W1b + (size_t)brow * 256 + nbase + bc4 * 4;

    float acc[8][4];
    #pragma unroll
    for (int i = 0; i < 8; i++)
        #pragma unroll
        for (int j = 0; j < 4; j++) acc[i][j] = 0.f;

    for (int kt = 0; kt < 256 / 16; kt++) {
        #pragma unroll
        for (int i = 0; i < 2; i++) {
            int f4  = tid + i * 256;
            int row = f4 >> 2;
            int kk  = (f4 & 3) * 4;
            float4 v = *(const float4*)(g_H1 + (size_t)(mbase + row) * 256 + kt * 16 + kk);
            As[(kk+0)*128 + row] = v.x;
            As[(kk+1)*128 + row] = v.y;
            As[(kk+2)*128 + row] = v.z;
            As[(kk+3)*128 + row] = v.w;
        }
        {
            float4 v = *(const float4*)(bsrc + (size_t)kt * 16 * 256);
            *(float4*)&Bs[brow * 64 + bc4 * 4] = v;
        }
        __syncthreads();
        #pragma unroll
        for (int k = 0; k < 16; k++) {
            float4 a0 = *(const float4*)&As[k * 128 + tym * 8];
            float4 a1 = *(const float4*)&As[k * 128 + tym * 8 + 4];
            float4 b  = *(const float4*)&Bs[k * 64 + txn * 4];
            float am[8] = {a0.x, a0.y, a0.z, a0.w, a1.x, a1.y, a1.z, a1.w};
            float bn[4] = {b.x, b.y, b.z, b.w};
            #pragma unroll
            for (int i = 0; i < 8; i++)
                #pragma unroll
                for (int j = 0; j < 4; j++) acc[i][j] += am[i] * bn[j];
        }
        __syncthreads();
    }

    #pragma unroll
    for (int j = 0; j < 4; j++) {
        const int n = nbase + txn * 4 + j;
        const float bv = b1b[n];
        #pragma unroll
        for (int i = 0; i < 8; i++) {
            int m = mbase + tym * 8 + i;
            g_W1[(size_t)m * 256 + n] = fabsf(acc[i][j] + bv);
        }
    }
}

// =========================================================================
// K4: final fused epilogue. One warp per row, lane = EMB index e (0..31).
//   hidden_e = elu( sum_a q_a * w1[a,e] + b1_e )
//   wf_e     = abs( sum_k HF_k * Wfb[k,e] + bfb_e )
//   v        = sum_e Hv_e * Wv2_e + bv2
//   q_tot    = sum_e hidden_e * wf_e + v
//   delu_e   = hidden_e < 0 ? exp(hidden_e) : 1
//   grad_a   = sum_e w1[a,e] * delu_e * wf_e
// =========================================================================
__device__ __forceinline__ float wred(float v) {
    #pragma unroll
    for (int o = 16; o > 0; o >>= 1) v += __shfl_xor_sync(0xFFFFFFFFu, v, o);
    return v;
}

__global__ __launch_bounds__(128) void k4_final(
    const float* __restrict__ agent_qs,
    const float* __restrict__ Wfb, const float* __restrict__ bfb,
    const float* __restrict__ Wv2, const float* __restrict__ bv2,
    float* __restrict__ out)
{
    __shared__ float wfb_sm[256 * 32];   // [k][e], lane e -> bank e, conflict-free
    __shared__ float hf_sm[4][256];
    __shared__ float wv2_sm[32];
    __shared__ float bfb_sm[32];

    const int tid = threadIdx.x;
    {
        float4* d = (float4*)wfb_sm;
        const float4* s = (const float4*)Wfb;
        for (int i = tid; i < 2048; i += 128) d[i] = s[i];
        if (tid < 32) { wv2_sm[tid] = Wv2[tid]; bfb_sm[tid] = bfb[tid]; }
    }
    __syncthreads();

    const int w = tid >> 5, lane = tid & 31;
    const size_t r = (size_t)blockIdx.x * 4 + w;

    float q[8];
    #pragma unroll
    for (int a = 0; a < 8; a++) q[a] = agent_qs[r * 8 + a];

    float w1r[8];
    const float* w1p = g_W1 + r * 256;
    #pragma unroll
    for (int a = 0; a < 8; a++) w1r[a] = w1p[a * 32 + lane];

    float x = g_B1[r * 32 + lane];
    #pragma unroll
    for (int a = 0; a < 8; a++) x += q[a] * w1r[a];
    const float h    = (x > 0.f) ? x : expm1f(x);
    const float delu = (h < 0.f) ? expf(h) : 1.f;

    // stage HF row
    const float* hfp = g_HF + r * 256;
    #pragma unroll
    for (int i = 0; i < 8; i++) hf_sm[w][lane + 32 * i] = hfp[lane + 32 * i];
    __syncwarp();

    float wf = bfb_sm[lane];
    const float4* hf4 = (const float4*)hf_sm[w];
    #pragma unroll 4
    for (int k4 = 0; k4 < 64; k4++) {
        float4 hv = hf4[k4];
        wf += hv.x * wfb_sm[(k4*4+0) * 32 + lane];
        wf += hv.y * wfb_sm[(k4*4+1) * 32 + lane];
        wf += hv.z * wfb_sm[(k4*4+2) * 32 + lane];
        wf += hv.w * wfb_sm[(k4*4+3) * 32 + lane];
    }
    wf = fabsf(wf);

    const float vsum = wred(g_Hv[r * 32 + lane] * wv2_sm[lane]);
    const float qt   = wred(h * wf);
    if (lane == 0) out[r] = qt + vsum + bv2[0];

    const float t = delu * wf;
    float* gout = out + BTOT;
    #pragma unroll
    for (int a = 0; a < 8; a++) {
        float s = wred(w1r[a] * t);
        if (lane == a) gout[r * 8 + a] = s;
    }
}

// =========================================================================
extern "C" void kernel_launch(void* const* d_in, const int* in_sizes, int n_in,
                              void* d_out, int out_size)
{
    (void)in_sizes; (void)n_in; (void)out_size;
    const float* agent_qs = (const float*)d_in[0];
    // d_in[1] = hist (unused), d_in[3] = obs (unused)
    const float* states = (const float*)d_in[2];
    const float* W_tok  = (const float*)d_in[4];
    const float* b_tok  = (const float*)d_in[5];
    const float* W_yfc  = (const float*)d_in[6];
    const float* b_yfc  = (const float*)d_in[7];
    const float* W1a    = (const float*)d_in[8];
    const float* b1a    = (const float*)d_in[9];
    const float* W1b    = (const float*)d_in[10];
    const float* b1b    = (const float*)d_in[11];
    const float* Wfa    = (const float*)d_in[12];
    const float* bfa    = (const float*)d_in[13];
    const float* Wfb    = (const float*)d_in[14];
    const float* bfb    = (const float*)d_in[15];
    const float* Wb1    = (const float*)d_in[16];
    const float* bb1    = (const float*)d_in[17];
    const float* Wv1    = (const float*)d_in[18];
    const float* bv1    = (const float*)d_in[19];
    const float* Wv2    = (const float*)d_in[20];
    const float* bv2    = (const float*)d_in[21];
    float* out = (float*)d_out;

    k1_embed<<<BTOT / 8, 64>>>(states, W_tok, b_tok, W_yfc, b_yfc);
    k2_gemm<<<dim3(9, BTOT / 128), 256>>>(W1a, b1a, Wfa, bfa, Wb1, bb1, Wv1, bv1);
    k3_gemm<<<dim3(4, BTOT / 128), 256>>>(W1b, b1b);
    k4_final<<<BTOT / 4, 128>>>(agent_qs, Wfb, bfb, Wv2, bv2, out);
}